// round 2
// baseline (speedup 1.0000x reference)
#include <cuda_runtime.h>
#include <math.h>
#include <float.h>

#define C_IN   64
#define C_OUT  128
#define HH     128
#define WW     128
#define BATCH  16
#define HO     126
#define WO     126
#define LL     (HO * WO)          /* 15876 */
#define KDIM   (C_IN * 9)         /* 576 */
#define NTOT   (BATCH * LL)       /* 254016 */
#define YSIZE  (BATCH * C_OUT * LL)

__device__ float g_wnT[KDIM * C_OUT];      // normalized weights, [k][co]
__device__ int   g_winners[BATCH * C_OUT];

// ---------------------------------------------------------------------------
// 1) L2-normalize each output filter; store transposed [k][co] for coalesced
//    GEMM A-tile loads.
// ---------------------------------------------------------------------------
__global__ void norm_kernel(const float* __restrict__ w) {
    int co = blockIdx.x;
    int tid = threadIdx.x;
    __shared__ float red[256];
    float s = 0.f;
    for (int k = tid; k < KDIM; k += 256) {
        float v = w[co * KDIM + k];
        s += v * v;
    }
    red[tid] = s;
    __syncthreads();
    for (int o = 128; o > 0; o >>= 1) {
        if (tid < o) red[tid] += red[tid + o];
        __syncthreads();
    }
    float nrm = sqrtf(red[0]);
    float inv = (nrm == 0.f) ? 1.f : (1.f / nrm);
    for (int k = tid; k < KDIM; k += 256) {
        g_wnT[k * C_OUT + co] = w[co * KDIM + k] * inv;
    }
}

// ---------------------------------------------------------------------------
// 2) Implicit-GEMM conv: y[co][n] = sum_k wnT[k][co] * im2col(x)[k][n]
//    Tile: BM=128 (all c_out), BN=128 spatial, BK=16. 256 threads, 8x8/thread.
// ---------------------------------------------------------------------------
__global__ __launch_bounds__(256)
void conv_kernel(const float* __restrict__ x, const float* __restrict__ bias,
                 float* __restrict__ y) {
    __shared__ float As[16][128];
    __shared__ float Bs[16][128];

    int tid = threadIdx.x;
    int n0 = blockIdx.x * 128;
    int tr = tid >> 4;   // 0..15
    int tc = tid & 15;   // 0..15

    // Precompute spatial base address for each of this thread's 8 B-tile slots
    int  xb[8];
    bool valid[8];
#pragma unroll
    for (int e = 0; e < 8; e++) {
        int idx = tid + e * 256;
        int p = idx & 127;
        int n = n0 + p;
        if (n < NTOT) {
            int b   = n / LL;
            int rem = n - b * LL;
            int ho  = rem / WO;
            int wo  = rem - ho * WO;
            xb[e] = ((b * C_IN) * HH + ho) * WW + wo;
            valid[e] = true;
        } else {
            xb[e] = 0;
            valid[e] = false;
        }
    }

    float acc[8][8];
#pragma unroll
    for (int i = 0; i < 8; i++)
#pragma unroll
        for (int j = 0; j < 8; j++) acc[i][j] = 0.f;

    for (int k0 = 0; k0 < KDIM; k0 += 16) {
#pragma unroll
        for (int e = 0; e < 8; e++) {
            int idx = tid + e * 256;
            int kl  = idx >> 7;    // 0..15
            int p   = idx & 127;
            As[kl][p] = g_wnT[(k0 + kl) * C_OUT + p];
            int k  = k0 + kl;
            int ci = k / 9;
            int r  = k - ci * 9;
            int kh = r / 3;
            int kw = r - kh * 3;
            float v = 0.f;
            if (valid[e]) v = x[xb[e] + ci * (HH * WW) + kh * WW + kw];
            Bs[kl][p] = v;
        }
        __syncthreads();

#pragma unroll
        for (int kk = 0; kk < 16; kk++) {
            float4 a0 = *(const float4*)&As[kk][tr * 4];
            float4 a1 = *(const float4*)&As[kk][64 + tr * 4];
            float4 b0 = *(const float4*)&Bs[kk][tc * 4];
            float4 b1 = *(const float4*)&Bs[kk][64 + tc * 4];
            float a[8] = {a0.x, a0.y, a0.z, a0.w, a1.x, a1.y, a1.z, a1.w};
            float b[8] = {b0.x, b0.y, b0.z, b0.w, b1.x, b1.y, b1.z, b1.w};
#pragma unroll
            for (int i = 0; i < 8; i++)
#pragma unroll
                for (int j = 0; j < 8; j++) acc[i][j] += a[i] * b[j];
        }
        __syncthreads();
    }

    // Epilogue: y[b, co, ho, wo] = acc + bias[co]
    int rows[8], cols[8];
#pragma unroll
    for (int i = 0; i < 4; i++) {
        rows[i]     = tr * 4 + i;
        rows[4 + i] = 64 + tr * 4 + i;
        cols[i]     = tc * 4 + i;
        cols[4 + i] = 64 + tc * 4 + i;
    }
#pragma unroll
    for (int j = 0; j < 8; j++) {
        int n = n0 + cols[j];
        if (n >= NTOT) continue;
        int b   = n / LL;
        int rem = n - b * LL;
        size_t base = (size_t)b * (C_OUT * LL) + rem;
#pragma unroll
        for (int i = 0; i < 8; i++) {
            int co = rows[i];
            y[base + (size_t)co * LL] = acc[i][j] + bias[co];
        }
    }
}

// ---------------------------------------------------------------------------
// 3) Winner-take-all: argmax over L per (b, co), first-index tie-break.
// ---------------------------------------------------------------------------
__global__ void argmax_kernel(const float* __restrict__ y) {
    int bc  = blockIdx.x;               // b*C_OUT + co; y offset = bc*LL
    int tid = threadIdx.x;
    const float* row = y + (size_t)bc * LL;

    float best = -FLT_MAX;
    int   bi   = 0x7fffffff;
    for (int l = tid; l < LL; l += 256) {
        float v = row[l];
        if (v > best) { best = v; bi = l; }   // keeps first index within thread
    }
    __shared__ float sv[256];
    __shared__ int   si[256];
    sv[tid] = best;
    si[tid] = bi;
    __syncthreads();
    for (int o = 128; o > 0; o >>= 1) {
        if (tid < o) {
            if (sv[tid + o] > sv[tid] ||
                (sv[tid + o] == sv[tid] && si[tid + o] < si[tid])) {
                sv[tid] = sv[tid + o];
                si[tid] = si[tid + o];
            }
        }
        __syncthreads();
    }
    if (tid == 0) g_winners[bc] = si[0];
}

// ---------------------------------------------------------------------------
// 4) delta_w[co][k] = mean_b x_patch[b, winner[b,co], k]
// ---------------------------------------------------------------------------
__global__ void deltaw_kernel(const float* __restrict__ x, float* __restrict__ out) {
    int t = blockIdx.x * blockDim.x + threadIdx.x;
    if (t >= C_OUT * KDIM) return;
    int co = t / KDIM;
    int k  = t - co * KDIM;
    int ci = k / 9;
    int r  = k - ci * 9;
    int kh = r / 3;
    int kw = r - kh * 3;
    float s = 0.f;
#pragma unroll
    for (int b = 0; b < BATCH; b++) {
        int l  = g_winners[b * C_OUT + co];
        int ho = l / WO;
        int wo = l - ho * WO;
        s += x[((b * C_IN + ci) * HH + ho + kh) * WW + wo + kw];
    }
    out[(size_t)YSIZE + t] = s * (1.f / 16.f);
}

// ---------------------------------------------------------------------------
extern "C" void kernel_launch(void* const* d_in, const int* in_sizes, int n_in,
                              void* d_out, int out_size) {
    const float* x    = (const float*)d_in[0];
    const float* w    = (const float*)d_in[1];
    const float* bias = (const float*)d_in[2];
    float* out = (float*)d_out;

    norm_kernel<<<C_OUT, 256>>>(w);
    conv_kernel<<<(NTOT + 127) / 128, 256>>>(x, bias, out);
    argmax_kernel<<<BATCH * C_OUT, 256>>>(out);
    deltaw_kernel<<<(C_OUT * KDIM + 255) / 256, 256>>>(x, out);
}

// round 4
// speedup vs baseline: 2.2103x; 2.2103x over previous
#include <cuda_runtime.h>
#include <math.h>
#include <float.h>
#include <stdint.h>

#define C_IN   64
#define C_OUT  128
#define HH     128
#define WW     128
#define BATCH  16
#define HO     126
#define WO     126
#define LL     (HO * WO)          /* 15876 */
#define KDIM   576
#define NTOT   (BATCH * LL)       /* 254016 */
#define NCHUNK 18
#define BK     32

__device__ float g_wn2[NCHUNK * C_OUT * BK];            // [chunk][co][kk] exact fp32 (refine)
__device__ float g_wA[NCHUNK * 4096];                   // tf32 bits, fragment-ordered
__device__ float g_xt[(size_t)BATCH * HH * WW * C_IN];  // NHWC x
__device__ int   g_winners[BATCH * C_OUT];

__device__ __forceinline__ uint32_t smem_u32(const void* p) {
    uint32_t a;
    asm("{ .reg .u64 t; cvta.to.shared.u64 t, %1; cvt.u32.u64 %0, t; }" : "=r"(a) : "l"(p));
    return a;
}
__device__ __forceinline__ uint32_t f2tf32(float f) {
    uint32_t r;
    asm("cvt.rna.tf32.f32 %0, %1;" : "=r"(r) : "f"(f));
    return r;
}
#define CP_ASYNC16(dst, src) asm volatile("cp.async.ca.shared.global [%0], [%1], 16;" :: "r"(dst), "l"(src) : "memory")
#define CP_COMMIT()          asm volatile("cp.async.commit_group;" ::: "memory")
#define CP_WAIT0()           asm volatile("cp.async.wait_group 0;" ::: "memory")

__device__ __forceinline__ void mma8(float* c, uint32_t a0, uint32_t a1, uint32_t a2, uint32_t a3,
                                     uint32_t b0, uint32_t b1) {
    asm volatile("mma.sync.aligned.m16n8k8.row.col.f32.tf32.tf32.f32 "
        "{%0,%1,%2,%3}, {%4,%5,%6,%7}, {%8,%9}, {%0,%1,%2,%3};"
        : "+f"(c[0]), "+f"(c[1]), "+f"(c[2]), "+f"(c[3])
        : "r"(a0), "r"(a1), "r"(a2), "r"(a3), "r"(b0), "r"(b1));
}

// ---------------------------------------------------------------------------
// 1) Normalize filters. Emit:
//    g_wn2[c][co][kk]  exact fp32 (for argmax refinement)
//    g_wA  tf32 bits in per-chunk MMA-fragment order
// ---------------------------------------------------------------------------
__global__ void norm_kernel(const float* __restrict__ w) {
    int co = blockIdx.x, tid = threadIdx.x;
    __shared__ float red[256];
    float s = 0.f;
    for (int k = tid; k < KDIM; k += 256) { float v = w[co * KDIM + k]; s += v * v; }
    red[tid] = s;
    __syncthreads();
    for (int o = 128; o > 0; o >>= 1) { if (tid < o) red[tid] += red[tid + o]; __syncthreads(); }
    float nrm = sqrtf(red[0]);
    float inv = (nrm == 0.f) ? 1.f : (1.f / nrm);

    int mwarp = co >> 6, mt = (co >> 4) & 3;
    int regb0 = (co >> 3) & 1, lanehi = (co & 7) << 2;
    for (int idx = tid; idx < KDIM; idx += 256) {
        int c = idx >> 5, kk = idx & 31;
        int r = c >> 1, ci = ((c & 1) << 5) + kk;
        float val = w[co * KDIM + ci * 9 + r] * inv;
        g_wn2[(c * C_OUT + co) * BK + kk] = val;
        int ks = kk >> 3;
        int lane = lanehi | (kk & 3);
        int reg = regb0 | (((kk >> 2) & 1) << 1);
        g_wA[c * 4096 + ((((mwarp * 4 + mt) * 4 + ks) * 32) + lane) * 4 + reg] =
            __uint_as_float(f2tf32(val));
    }
}

// ---------------------------------------------------------------------------
// 2) NCHW -> NHWC transpose
// ---------------------------------------------------------------------------
__global__ __launch_bounds__(256) void transpose_kernel(const float* __restrict__ x) {
    __shared__ float s[128][65];
    int bh = blockIdx.x;
    int b = bh >> 7, h = bh & 127;
    int tid = threadIdx.x;
#pragma unroll 4
    for (int step = 0; step < 32; step++) {
        int ci = step * 2 + (tid >> 7);
        int wq = tid & 127;
        s[wq][ci] = x[(((size_t)(b * C_IN + ci) * HH) + h) * WW + wq];
    }
    __syncthreads();
#pragma unroll 4
    for (int step = 0; step < 32; step++) {
        int wq = step * 4 + (tid >> 6);
        int ci = tid & 63;
        g_xt[((size_t)((b * HH + h) * WW + wq)) * C_IN + ci] = s[wq][ci];
    }
}

// ---------------------------------------------------------------------------
// 3) Conv as tf32 mma.sync GEMM. BM=128, BN=128, BK=32, 8 warps (2m x 4n),
//    warp tile 64x32, fragments stored pre-permuted in smem.
//    smem: 2 bufs x (A 16KB + B 16KB) = 64KB dynamic.
// ---------------------------------------------------------------------------
__global__ __launch_bounds__(256, 2)
void conv_mma_kernel(const float* __restrict__ bias, float* __restrict__ y) {
    extern __shared__ char smem[];
    uint32_t sbase = smem_u32(smem);

    int tid = threadIdx.x;
    int wid = tid >> 5, lane = tid & 31;
    int n0 = blockIdx.x * 128;

    // ------- B loader state: 2 threads per n-row, 16 k-values each -------
    int nl = tid >> 1, half = tid & 1;
    int n = n0 + nl;
    bool valid = (n < NTOT);
    long xbase = 0;
    if (valid) {
        int b = n / LL; int rem = n - b * LL;
        int ho = rem / WO; int wo = rem - ho * WO;
        xbase = ((long)(b * HH + ho) * WW + wo) * C_IN;
    }
    int nwarp_st = nl >> 5, nt_st = (nl >> 3) & 3, lanebase = (nl & 7) << 2;

    float fB[16];

    // ------- compute-side ids -------
    int mwarp = wid >> 2, nwarp = wid & 3;

    float acc[4][4][4];
#pragma unroll
    for (int i = 0; i < 4; i++)
#pragma unroll
        for (int j = 0; j < 4; j++)
#pragma unroll
            for (int q = 0; q < 4; q++) acc[i][j][q] = 0.f;

    // ---- prologue: chunk 0 ----
    {
        const float4* p = (const float4*)&g_xt[xbase + half * 16];   // chunk0: kh=kw=0, ci0=0
        if (valid) {
#pragma unroll
            for (int q = 0; q < 4; q++) {
                float4 v = p[q];
                fB[q * 4 + 0] = v.x; fB[q * 4 + 1] = v.y; fB[q * 4 + 2] = v.z; fB[q * 4 + 3] = v.w;
            }
        } else {
#pragma unroll
            for (int q = 0; q < 16; q++) fB[q] = 0.f;
        }
        // STS B buf0
        uint32_t* Bs = (uint32_t*)(smem + 16384);
#pragma unroll
        for (int g = 0; g < 2; g++) {
            int ks = half * 2 + g;
#pragma unroll
            for (int tig = 0; tig < 4; tig++) {
                uint2 v;
                v.x = f2tf32(fB[g * 8 + tig]);
                v.y = f2tf32(fB[g * 8 + tig + 4]);
                *(uint2*)&Bs[(((nwarp_st * 4 + nt_st) * 4 + ks) * 32 + lanebase + tig) * 2] = v;
            }
        }
        // cp.async A buf0
        const char* src = (const char*)(g_wA) + tid * 16;
        uint32_t dst = sbase + tid * 16;
#pragma unroll
        for (int q = 0; q < 4; q++) CP_ASYNC16(dst + q * 4096, src + q * 4096);
        CP_COMMIT();
    }

    int cur = 0;
    for (int c = 0; c < NCHUNK; c++) {
        CP_WAIT0();
        __syncthreads();

        bool more = (c + 1 < NCHUNK);
        if (more) {
            // issue next A copy
            const char* src = (const char*)(g_wA + (c + 1) * 4096) + tid * 16;
            uint32_t dst = sbase + (cur ^ 1) * 32768 + tid * 16;
#pragma unroll
            for (int q = 0; q < 4; q++) CP_ASYNC16(dst + q * 4096, src + q * 4096);
            CP_COMMIT();
            // prefetch next B into regs
            int cn = c + 1;
            int r = cn >> 1;
            int kh = r / 3, kw = r - kh * 3;
            if (valid) {
                const float4* p = (const float4*)&g_xt[xbase + (long)(kh * WW + kw) * C_IN +
                                                       ((cn & 1) << 5) + half * 16];
#pragma unroll
                for (int q = 0; q < 4; q++) {
                    float4 v = p[q];
                    fB[q * 4 + 0] = v.x; fB[q * 4 + 1] = v.y; fB[q * 4 + 2] = v.z; fB[q * 4 + 3] = v.w;
                }
            }
        }

        // ---- compute on buf cur ----
        const float4* As = (const float4*)(smem + cur * 32768);
        const float2* Bs = (const float2*)(smem + cur * 32768 + 16384);
#pragma unroll
        for (int ks = 0; ks < 4; ks++) {
            float4 a[4];
            float2 b[4];
#pragma unroll
            for (int mt = 0; mt < 4; mt++)
                a[mt] = As[((mwarp * 4 + mt) * 4 + ks) * 32 + lane];
#pragma unroll
            for (int nt = 0; nt < 4; nt++)
                b[nt] = Bs[((nwarp * 4 + nt) * 4 + ks) * 32 + lane];
#pragma unroll
            for (int mt = 0; mt < 4; mt++)
#pragma unroll
                for (int nt = 0; nt < 4; nt++)
                    mma8(acc[mt][nt],
                         __float_as_uint(a[mt].x), __float_as_uint(a[mt].y),
                         __float_as_uint(a[mt].z), __float_as_uint(a[mt].w),
                         __float_as_uint(b[nt].x), __float_as_uint(b[nt].y));
        }

        if (more) {
            // STS next B (fragment order) into buf cur^1
            uint32_t* Bw = (uint32_t*)(smem + (cur ^ 1) * 32768 + 16384);
#pragma unroll
            for (int g = 0; g < 2; g++) {
                int ks = half * 2 + g;
#pragma unroll
                for (int tig = 0; tig < 4; tig++) {
                    uint2 v;
                    v.x = f2tf32(fB[g * 8 + tig]);
                    v.y = f2tf32(fB[g * 8 + tig + 4]);
                    *(uint2*)&Bw[(((nwarp_st * 4 + nt_st) * 4 + ks) * 32 + lanebase + tig) * 2] = v;
                }
            }
        }
        cur ^= 1;
    }

    // ---- epilogue ----
    int groupID = lane >> 2, tig = lane & 3;
#pragma unroll
    for (int nt = 0; nt < 4; nt++) {
        int nn = n0 + nwarp * 32 + nt * 8 + tig * 2;   // even
        if (nn >= NTOT) continue;
        int bb = nn / LL;
        int l = nn - bb * LL;
        size_t base = (size_t)bb * (C_OUT * LL) + l;
#pragma unroll
        for (int mt = 0; mt < 4; mt++) {
#pragma unroll
            for (int rh = 0; rh < 2; rh++) {
                int co = mwarp * 64 + mt * 16 + groupID + rh * 8;
                float bco = bias[co];
                float2 v;
                v.x = acc[mt][nt][rh * 2 + 0] + bco;
                v.y = acc[mt][nt][rh * 2 + 1] + bco;
                *(float2*)&y[base + (size_t)co * LL] = v;
            }
        }
    }
}

// ---------------------------------------------------------------------------
// 4) argmax (tf32 y) + exact fp32 refinement of near-max candidates
// ---------------------------------------------------------------------------
__global__ void argmax_refine_kernel(const float* __restrict__ y) {
    int bc = blockIdx.x, tid = threadIdx.x;
    const float* row = y + (size_t)bc * LL;
    int b = bc >> 7, co = bc & 127;
    __shared__ float sv[256];
    __shared__ int   si[256];

    float m = -FLT_MAX;
    for (int l = tid; l < LL; l += 256) { float vv = row[l]; if (vv > m) m = vv; }
    sv[tid] = m;
    __syncthreads();
    for (int o = 128; o > 0; o >>= 1) { if (tid < o) sv[tid] = fmaxf(sv[tid], sv[tid + o]); __syncthreads(); }
    float thresh = sv[0] - 0.05f;
    __syncthreads();

    float best = -FLT_MAX;
    int bi = 0x7fffffff;
    for (int l = tid; l < LL; l += 256) {
        float vv = row[l];
        if (vv >= thresh) {
            int ho = l / WO, wo = l - ho * WO;
            float acc = 0.f;
            for (int c = 0; c < NCHUNK; c++) {
                int r = c >> 1, kh = r / 3, kw = r - kh * 3;
                const float* wp = &g_wn2[(c * C_OUT + co) * BK];
                const float* xp = &g_xt[((size_t)((b * HH + ho + kh) * WW) + (wo + kw)) * C_IN + ((c & 1) << 5)];
#pragma unroll
                for (int kk = 0; kk < BK; kk++) acc += wp[kk] * xp[kk];
            }
            if (acc > best || (acc == best && l < bi)) { best = acc; bi = l; }
        }
    }
    sv[tid] = best; si[tid] = bi;
    __syncthreads();
    for (int o = 128; o > 0; o >>= 1) {
        if (tid < o) {
            if (sv[tid + o] > sv[tid] || (sv[tid + o] == sv[tid] && si[tid + o] < si[tid])) {
                sv[tid] = sv[tid + o]; si[tid] = si[tid + o];
            }
        }
        __syncthreads();
    }
    if (tid == 0) g_winners[bc] = si[0];
}

// ---------------------------------------------------------------------------
// 5) delta_w[co][k] = mean_b winning patch
// ---------------------------------------------------------------------------
__global__ void deltaw_kernel(const float* __restrict__ x, float* __restrict__ out) {
    int t = blockIdx.x * blockDim.x + threadIdx.x;
    if (t >= C_OUT * KDIM) return;
    int co = t / KDIM;
    int k = t - co * KDIM;
    int ci = k / 9;
    int r = k - ci * 9;
    int kh = r / 3, kw = r - kh * 3;
    float s = 0.f;
#pragma unroll
    for (int b = 0; b < BATCH; b++) {
        int l = g_winners[b * C_OUT + co];
        int ho = l / WO;
        int wo = l - ho * WO;
        s += x[((size_t)(b * C_IN + ci) * HH + ho + kh) * WW + wo + kw];
    }
    out[(size_t)BATCH * C_OUT * LL + t] = s * (1.f / 16.f);
}

// ---------------------------------------------------------------------------
extern "C" void kernel_launch(void* const* d_in, const int* in_sizes, int n_in,
                              void* d_out, int out_size) {
    const float* x    = (const float*)d_in[0];
    const float* w    = (const float*)d_in[1];
    const float* bias = (const float*)d_in[2];
    float* out = (float*)d_out;

    cudaFuncSetAttribute(conv_mma_kernel,
                         cudaFuncAttributeMaxDynamicSharedMemorySize, 65536);

    norm_kernel<<<C_OUT, 256>>>(w);
    transpose_kernel<<<BATCH * HH, 256>>>(x);
    conv_mma_kernel<<<(NTOT + 127) / 128, 256, 65536>>>(bias, out);
    argmax_refine_kernel<<<BATCH * C_OUT, 256>>>(out);
    deltaw_kernel<<<(C_OUT * KDIM + 255) / 256, 256>>>(x, out);
}